// round 3
// baseline (speedup 1.0000x reference)
#include <cuda_runtime.h>
#include <math.h>

// Problem constants (shapes fixed by the dataset)
#define NUM_CLASSES 100000
#define ROWF 52      // floats per scratch row: [mn0,mx0,...,mn24,mx24,area,pad]
#define ROW4 13      // float4 per scratch row
#define PPB  256     // pairs per block in the pair kernel
#define STRIDE4 27   // smem stride (float4) per pair: 26 used + 1 pad (odd -> conflict-free LDS.128)
#define PRE_ROWS 64  // rows per block in precompute (keeps static smem < 48KB)
#define EMB_BOUND 10000.0f

// Scratch: transformed table (20.8 MB) + accumulator. Static __device__ globals
// (runtime allocation is forbidden by the harness).
__device__ float4 g_scratch[NUM_CLASSES * ROW4];
__device__ double g_acc;

// ---------------------------------------------------------------------------
// Kernel 1: transform class_embeds -> [mn,mx interleaved, area] rows.
// Coalesced in and out via shared-memory staging.
// Static smem: 64*50*4 + 64*52*4 = 26,112 B  (< 48KB static limit)
// ---------------------------------------------------------------------------
__global__ __launch_bounds__(128)
void precompute_kernel(const float* __restrict__ embeds, int num_classes) {
    __shared__ float s_in[PRE_ROWS * 50];
    __shared__ float s_out[PRE_ROWS * ROWF];

    int b0 = blockIdx.x * PRE_ROWS;
    int n  = num_classes - b0;
    if (n > PRE_ROWS) n = PRE_ROWS;
    if (n <= 0) return;

    // Coalesced load of n contiguous rows (50 floats each)
    for (int i = threadIdx.x; i < n * 50; i += blockDim.x)
        s_in[i] = embeds[b0 * 50 + i];
    __syncthreads();

    int t = threadIdx.x;
    if (t < n) {
        float area = 1.0f;
        #pragma unroll
        for (int k = 0; k < 25; k++) {
            float c = s_in[t * 50 + k];
            float o = fabsf(s_in[t * 50 + 25 + k]);
            s_out[t * ROWF + 2 * k]     = c - o;   // mn
            s_out[t * ROWF + 2 * k + 1] = c + o;   // mx
            area *= 2.0f * o;
        }
        s_out[t * ROWF + 50] = area;
        s_out[t * ROWF + 51] = 0.0f;
    }
    __syncthreads();

    // Coalesced store to global scratch
    float* gs = (float*)g_scratch;
    for (int i = threadIdx.x; i < n * ROWF; i += blockDim.x)
        gs[b0 * ROWF + i] = s_out[i];

    if (blockIdx.x == 0 && threadIdx.x == 0) g_acc = 0.0;
}

// ---------------------------------------------------------------------------
// Kernel 2: per-pair inclusion loss with cooperative smem gather.
// Each block handles PPB pairs. Gather phase: consecutive threads load
// consecutive float4 chunks of the same scratch row, so each LDG.128 touches
// only a few 128B lines (avoids the 32-wavefront divergent-gather penalty).
// Dynamic smem: 256*27*16 + 2*256*4 = 112,640 B (opt-in via cudaFuncSetAttribute)
// ---------------------------------------------------------------------------
__global__ __launch_bounds__(PPB)
void pair_kernel(const int* __restrict__ nf1, int nPairs) {
    extern __shared__ float4 sm4[];                 // PPB*STRIDE4 float4
    int* sIdx = (int*)&sm4[PPB * STRIDE4];          // 2*PPB ints

    int p0  = blockIdx.x * PPB;
    int tid = threadIdx.x;
    int np  = nPairs - p0;
    if (np > PPB) np = PPB;

    // Load pair indices (coalesced int2)
    if (tid < np) {
        int2 ij = ((const int2*)nf1)[p0 + tid];
        sIdx[2 * tid]     = ij.x;  // C
        sIdx[2 * tid + 1] = ij.y;  // D
    }
    __syncthreads();

    // Cooperative gather: 26 float4 chunks per pair (13 for C, 13 for D)
    int total = np * 26;
    for (int i = tid; i < total; i += PPB) {
        int pair  = i / 26;
        int sub   = i - pair * 26;
        int which = (sub >= 13) ? 1 : 0;
        int chunk = sub - which * 13;
        int row   = sIdx[2 * pair + which];
        sm4[pair * STRIDE4 + sub] = g_scratch[row * ROW4 + chunk];
    }
    __syncthreads();

    // Compute phase: thread t handles pair t
    float ssq = 0.0f;
    if (tid < np) {
        const float4* P = &sm4[tid * STRIDE4];      // [0..12]=C, [13..25]=D
        float prod = 1.0f;
        #pragma unroll
        for (int j = 0; j < 12; j++) {
            float4 c = P[j];
            float4 d = P[13 + j];
            prod *= fmaxf(fminf(c.y, d.y) - fmaxf(c.x, d.x), 0.0f);  // dim 2j
            prod *= fmaxf(fminf(c.w, d.w) - fmaxf(c.z, d.z), 0.0f);  // dim 2j+1
        }
        float4 c12 = P[12];
        float4 d12 = P[25];
        prod *= fmaxf(fminf(c12.y, d12.y) - fmaxf(c12.x, d12.x), 0.0f);  // dim 24
        float area = c12.z;

        float loss;
        if (area == 0.0f)      loss = 0.0f;
        else if (isinf(area))  loss = 1.0f - prod * (1.0f / (2.0f * EMB_BOUND));
        else                   loss = 1.0f - prod / area;
        loss = fmaxf(loss, 0.0f);
        ssq = loss * loss;
    }

    // Block reduction
    #pragma unroll
    for (int off = 16; off; off >>= 1)
        ssq += __shfl_down_sync(0xffffffffu, ssq, off);

    __shared__ float warpSums[PPB / 32];
    if ((tid & 31) == 0) warpSums[tid >> 5] = ssq;
    __syncthreads();
    if (tid < PPB / 32) {
        float v = warpSums[tid];
        #pragma unroll
        for (int off = (PPB / 64); off; off >>= 1)
            v += __shfl_down_sync(0xffu, v, off);
        if (tid == 0) atomicAdd(&g_acc, (double)v);
    }
}

// ---------------------------------------------------------------------------
// Kernel 3: finalize
// ---------------------------------------------------------------------------
__global__ void finalize_kernel(float* __restrict__ out) {
    out[0] = sqrtf((float)g_acc);
}

extern "C" void kernel_launch(void* const* d_in, const int* in_sizes, int n_in,
                              void* d_out, int out_size) {
    const float* embeds = (const float*)d_in[0];   // class_embeds [100000, 50]
    const int*   nf1    = (const int*)d_in[1];     // nf1_data    [2000000, 2]

    int num_classes = in_sizes[0] / 50;
    if (num_classes > NUM_CLASSES) num_classes = NUM_CLASSES;
    int nPairs = in_sizes[1] / 2;

    // Precompute transformed table + zero accumulator
    int pre_blocks = (num_classes + PRE_ROWS - 1) / PRE_ROWS;
    precompute_kernel<<<pre_blocks, 128>>>(embeds, num_classes);

    // Pair kernel: needs >48KB dynamic smem (opt-in; host call, not captured)
    int smem_bytes = PPB * STRIDE4 * (int)sizeof(float4) + 2 * PPB * (int)sizeof(int);
    cudaFuncSetAttribute(pair_kernel,
                         cudaFuncAttributeMaxDynamicSharedMemorySize, smem_bytes);
    int pair_blocks = (nPairs + PPB - 1) / PPB;
    pair_kernel<<<pair_blocks, PPB, smem_bytes>>>(nf1, nPairs);

    finalize_kernel<<<1, 1>>>((float*)d_out);
}

// round 8
// speedup vs baseline: 1.2103x; 1.2103x over previous
#include <cuda_runtime.h>
#include <math.h>

// Problem constants (shapes fixed by the dataset)
#define NUM_CLASSES 100000
#define ROWF 52      // floats per scratch row: [mn0,mx0,...,mn24,mx24,area,pad]
#define ROW4 13      // float4 per scratch row
#define PPB  128     // pairs per block in the pair kernel (smem 56.3KB -> 4 blocks/SM)
#define STRIDE4 27   // smem stride (float4) per pair; 108-word stride -> conflict-free LDS.128 phases
#define EMB_BOUND 10000.0f

// Scratch: transformed table (20.8 MB) + accumulator. Static __device__ globals
// (runtime allocation is forbidden by the harness).
__device__ float4 g_scratch[NUM_CLASSES * ROW4];
__device__ double g_acc;

// ---------------------------------------------------------------------------
// Kernel 1: transform class_embeds -> [mn,mx interleaved, area] rows.
// One warp per row: lanes 0..24 each own one dim. 2 coalesced LDG.32 per lane,
// shfl-xor product reduction for the area, coalesced float2 stores. No smem.
// ---------------------------------------------------------------------------
__global__ __launch_bounds__(256)
void precompute_kernel(const float* __restrict__ embeds, int num_classes) {
    int gtid = blockIdx.x * blockDim.x + threadIdx.x;
    if (gtid == 0) g_acc = 0.0;

    int warp = gtid >> 5;
    int lane = threadIdx.x & 31;
    if (warp >= num_classes) return;

    float c = 0.0f, o = 0.0f, part = 1.0f;
    if (lane < 25) {
        c = embeds[warp * 50 + lane];
        o = fabsf(embeds[warp * 50 + 25 + lane]);
        part = 2.0f * o;
    }
    // Product across all 32 lanes (idle lanes contribute 1.0)
    #pragma unroll
    for (int off = 16; off; off >>= 1)
        part *= __shfl_xor_sync(0xffffffffu, part, off);

    float* gs = (float*)g_scratch;
    if (lane < 25) {
        float2 v = make_float2(c - o, c + o);               // (mn, mx)
        *(float2*)(gs + (size_t)warp * ROWF + 2 * lane) = v; // 8B-aligned (208B rows)
    }
    if (lane == 25) {
        gs[(size_t)warp * ROWF + 50] = part;
        gs[(size_t)warp * ROWF + 51] = 0.0f;
    }
}

// ---------------------------------------------------------------------------
// Kernel 2: per-pair inclusion loss with cp.async cooperative smem gather.
// 128 pairs/block, 56.3KB dyn smem -> 4 resident blocks/SM. Gather is a fully
// unrolled 26-deep cp.async.cg stream per thread (no LDG->STS scoreboard
// dependency, MLP ~26), so L2 latency is overlapped within and across blocks.
// ---------------------------------------------------------------------------
__global__ __launch_bounds__(PPB, 4)
void pair_kernel(const int* __restrict__ nf1, int nPairs) {
    extern __shared__ float4 sm4[];                 // PPB*STRIDE4 float4
    int* sIdx = (int*)&sm4[PPB * STRIDE4];          // 2*PPB ints

    int p0  = blockIdx.x * PPB;
    int tid = threadIdx.x;
    int np  = nPairs - p0;
    if (np > PPB) np = PPB;

    // Load pair indices (coalesced int2)
    if (tid < np) {
        int2 ij = ((const int2*)nf1)[p0 + tid];
        sIdx[2 * tid]     = ij.x;  // C
        sIdx[2 * tid + 1] = ij.y;  // D
    }
    __syncthreads();

    // Cooperative gather: 26 float4 chunks per pair (13 C + 13 D), cp.async.
    if (np == PPB) {
        #pragma unroll
        for (int k = 0; k < 26; k++) {
            int i     = tid + k * PPB;
            int pair  = i / 26;
            int sub   = i - pair * 26;
            int which = (sub >= 13) ? 1 : 0;
            int chunk = sub - which * 13;
            int row   = sIdx[2 * pair + which];
            const float4* src = &g_scratch[(size_t)row * ROW4 + chunk];
            unsigned dst = (unsigned)__cvta_generic_to_shared(&sm4[pair * STRIDE4 + sub]);
            asm volatile("cp.async.cg.shared.global [%0], [%1], 16;\n"
                         :: "r"(dst), "l"(src));
        }
    } else {
        int total = np * 26;
        for (int i = tid; i < total; i += PPB) {
            int pair  = i / 26;
            int sub   = i - pair * 26;
            int which = (sub >= 13) ? 1 : 0;
            int chunk = sub - which * 13;
            int row   = sIdx[2 * pair + which];
            const float4* src = &g_scratch[(size_t)row * ROW4 + chunk];
            unsigned dst = (unsigned)__cvta_generic_to_shared(&sm4[pair * STRIDE4 + sub]);
            asm volatile("cp.async.cg.shared.global [%0], [%1], 16;\n"
                         :: "r"(dst), "l"(src));
        }
    }
    asm volatile("cp.async.commit_group;\n" ::: "memory");
    asm volatile("cp.async.wait_group 0;\n" ::: "memory");
    __syncthreads();

    // Compute phase: thread t handles pair t
    float ssq = 0.0f;
    if (tid < np) {
        const float4* P = &sm4[tid * STRIDE4];      // [0..12]=C, [13..25]=D
        float prod = 1.0f;
        #pragma unroll
        for (int j = 0; j < 12; j++) {
            float4 c = P[j];
            float4 d = P[13 + j];
            prod *= fmaxf(fminf(c.y, d.y) - fmaxf(c.x, d.x), 0.0f);  // dim 2j
            prod *= fmaxf(fminf(c.w, d.w) - fmaxf(c.z, d.z), 0.0f);  // dim 2j+1
        }
        float4 c12 = P[12];
        float4 d12 = P[25];
        prod *= fmaxf(fminf(c12.y, d12.y) - fmaxf(c12.x, d12.x), 0.0f);  // dim 24
        float area = c12.z;

        float loss;
        if (area == 0.0f)      loss = 0.0f;
        else if (isinf(area))  loss = 1.0f - prod * (1.0f / (2.0f * EMB_BOUND));
        else                   loss = 1.0f - prod / area;
        loss = fmaxf(loss, 0.0f);
        ssq = loss * loss;
    }

    // Block reduction (4 warps)
    #pragma unroll
    for (int off = 16; off; off >>= 1)
        ssq += __shfl_down_sync(0xffffffffu, ssq, off);

    __shared__ float warpSums[PPB / 32];
    if ((tid & 31) == 0) warpSums[tid >> 5] = ssq;
    __syncthreads();
    if (tid == 0) {
        float v = warpSums[0] + warpSums[1] + warpSums[2] + warpSums[3];
        atomicAdd(&g_acc, (double)v);
    }
}

// ---------------------------------------------------------------------------
// Kernel 3: finalize
// ---------------------------------------------------------------------------
__global__ void finalize_kernel(float* __restrict__ out) {
    out[0] = sqrtf((float)g_acc);
}

extern "C" void kernel_launch(void* const* d_in, const int* in_sizes, int n_in,
                              void* d_out, int out_size) {
    const float* embeds = (const float*)d_in[0];   // class_embeds [100000, 50]
    const int*   nf1    = (const int*)d_in[1];     // nf1_data    [2000000, 2]

    int num_classes = in_sizes[0] / 50;
    if (num_classes > NUM_CLASSES) num_classes = NUM_CLASSES;
    int nPairs = in_sizes[1] / 2;

    // Precompute transformed table (warp per row) + zero accumulator
    int pre_blocks = (num_classes * 32 + 255) / 256;
    precompute_kernel<<<pre_blocks, 256>>>(embeds, num_classes);

    // Pair kernel: 56.3KB dyn smem (opt-in; host call, not captured as a node)
    int smem_bytes = PPB * STRIDE4 * (int)sizeof(float4) + 2 * PPB * (int)sizeof(int);
    cudaFuncSetAttribute(pair_kernel,
                         cudaFuncAttributeMaxDynamicSharedMemorySize, smem_bytes);
    int pair_blocks = (nPairs + PPB - 1) / PPB;
    pair_kernel<<<pair_blocks, PPB, smem_bytes>>>(nf1, nPairs);

    finalize_kernel<<<1, 1>>>((float*)d_out);
}

// round 9
// speedup vs baseline: 1.4440x; 1.1931x over previous
#include <cuda_runtime.h>
#include <math.h>

// Problem constants (shapes fixed by the dataset)
#define NUM_CLASSES 100000
#define ROWF 52      // floats per scratch row: [mn0,mx0,...,mn24,mx24,area,pad]
#define ROW4 13      // float4 per scratch row
#define PPB  120     // pairs per tile (2 stages -> 105.6KB smem -> 2 blocks/SM)
#define NTHR 128     // threads per block in pair kernel
#define STRIDE4 27   // smem stride (float4) per pair; odd 108-word stride -> conflict-free LDS.128
#define EMB_BOUND 10000.0f

// Scratch: transformed table (20.8 MB) + accumulator. Static __device__ globals
// (runtime allocation is forbidden by the harness).
__device__ float4 g_scratch[NUM_CLASSES * ROW4];
__device__ double g_acc;

// ---------------------------------------------------------------------------
// Kernel 1: transform class_embeds -> [mn,mx interleaved, area] rows.
// One warp per row: lanes 0..24 each own one dim; shfl-xor product for area.
// ---------------------------------------------------------------------------
__global__ __launch_bounds__(256)
void precompute_kernel(const float* __restrict__ embeds, int num_classes) {
    int gtid = blockIdx.x * blockDim.x + threadIdx.x;
    if (gtid == 0) g_acc = 0.0;

    int warp = gtid >> 5;
    int lane = threadIdx.x & 31;
    if (warp >= num_classes) return;

    float c = 0.0f, o = 0.0f, part = 1.0f;
    if (lane < 25) {
        c = embeds[warp * 50 + lane];
        o = fabsf(embeds[warp * 50 + 25 + lane]);
        part = 2.0f * o;
    }
    #pragma unroll
    for (int off = 16; off; off >>= 1)
        part *= __shfl_xor_sync(0xffffffffu, part, off);

    float* gs = (float*)g_scratch;
    if (lane < 25) {
        float2 v = make_float2(c - o, c + o);                // (mn, mx)
        *(float2*)(gs + (size_t)warp * ROWF + 2 * lane) = v;
    }
    if (lane == 25) {
        gs[(size_t)warp * ROWF + 50] = part;
        gs[(size_t)warp * ROWF + 51] = 0.0f;
    }
}

// ---------------------------------------------------------------------------
// Kernel 2: PERSISTENT pair kernel, double-buffered cp.async pipeline.
// Each block loops over tiles of PPB pairs (grid-strided). While computing
// tile t it already has tile t+1's cp.async gather in flight (wait_group 1),
// so steady state is L2-throughput-bound instead of L2-latency-bound.
// Loss squares accumulate in registers; ONE atomicAdd per block at the end.
// ---------------------------------------------------------------------------
__global__ __launch_bounds__(NTHR, 2)
void pair_kernel(const int* __restrict__ nf1, int nPairs, int nTiles) {
    extern __shared__ float4 sm4[];                  // 2 * PPB * STRIDE4 float4
    int* sIdx = (int*)&sm4[2 * PPB * STRIDE4];       // 2 * 2*PPB ints

    int tid = threadIdx.x;
    float ssq_acc = 0.0f;

    int tile = blockIdx.x;
    int stride = gridDim.x;
    int buf = 0;

    // ---- prologue: stage first tile into buffer 0 ----
    if (tile < nTiles) {
        int p0 = tile * PPB;
        int np = nPairs - p0; if (np > PPB) np = PPB;
        if (tid < np) {
            int2 ij = ((const int2*)nf1)[p0 + tid];
            sIdx[2 * tid]     = ij.x;
            sIdx[2 * tid + 1] = ij.y;
        }
        __syncthreads();
        int total = np * 26;
        for (int i = tid; i < total; i += NTHR) {
            int pair  = i / 26;
            int sub   = i - pair * 26;
            int which = (sub >= 13) ? 1 : 0;
            int chunk = sub - which * 13;
            int row   = sIdx[2 * pair + which];
            const float4* src = &g_scratch[(size_t)row * ROW4 + chunk];
            unsigned dst = (unsigned)__cvta_generic_to_shared(&sm4[pair * STRIDE4 + sub]);
            asm volatile("cp.async.cg.shared.global [%0], [%1], 16;\n" :: "r"(dst), "l"(src));
        }
        asm volatile("cp.async.commit_group;\n" ::: "memory");
    }

    // ---- main pipeline loop ----
    for (; tile < nTiles; tile += stride) {
        int next    = tile + stride;
        int nb      = buf ^ 1;
        bool hasNxt = (next < nTiles);

        // Stage next tile's indices (overlaps with in-flight gather of cur)
        int nnp = 0;
        if (hasNxt) {
            int np0 = next * PPB;
            nnp = nPairs - np0; if (nnp > PPB) nnp = PPB;
            if (tid < nnp) {
                int2 ij = ((const int2*)nf1)[np0 + tid];
                sIdx[2 * PPB * nb + 2 * tid]     = ij.x;
                sIdx[2 * PPB * nb + 2 * tid + 1] = ij.y;
            }
        }
        __syncthreads();   // next idx visible; buffer nb free (prev compute done)

        // Issue next tile's gather
        if (hasNxt) {
            int total = nnp * 26;
            for (int i = tid; i < total; i += NTHR) {
                int pair  = i / 26;
                int sub   = i - pair * 26;
                int which = (sub >= 13) ? 1 : 0;
                int chunk = sub - which * 13;
                int row   = sIdx[2 * PPB * nb + 2 * pair + which];
                const float4* src = &g_scratch[(size_t)row * ROW4 + chunk];
                unsigned dst = (unsigned)__cvta_generic_to_shared(
                    &sm4[nb * PPB * STRIDE4 + pair * STRIDE4 + sub]);
                asm volatile("cp.async.cg.shared.global [%0], [%1], 16;\n" :: "r"(dst), "l"(src));
            }
            asm volatile("cp.async.commit_group;\n" ::: "memory");
            asm volatile("cp.async.wait_group 1;\n" ::: "memory");  // cur done, next in flight
        } else {
            asm volatile("cp.async.wait_group 0;\n" ::: "memory");
        }
        __syncthreads();   // cur tile data visible to all threads

        // Compute current tile
        int p0 = tile * PPB;
        int np = nPairs - p0; if (np > PPB) np = PPB;
        if (tid < np) {
            const float4* P = &sm4[buf * PPB * STRIDE4 + tid * STRIDE4];
            float prod = 1.0f;
            #pragma unroll
            for (int j = 0; j < 12; j++) {
                float4 c = P[j];
                float4 d = P[13 + j];
                prod *= fmaxf(fminf(c.y, d.y) - fmaxf(c.x, d.x), 0.0f);
                prod *= fmaxf(fminf(c.w, d.w) - fmaxf(c.z, d.z), 0.0f);
            }
            float4 c12 = P[12];
            float4 d12 = P[25];
            prod *= fmaxf(fminf(c12.y, d12.y) - fmaxf(c12.x, d12.x), 0.0f);
            float area = c12.z;

            float loss;
            if (area == 0.0f)      loss = 0.0f;
            else if (isinf(area))  loss = 1.0f - prod * (1.0f / (2.0f * EMB_BOUND));
            else                   loss = 1.0f - prod / area;
            loss = fmaxf(loss, 0.0f);
            ssq_acc += loss * loss;
        }
        buf = nb;
    }

    // ---- epilogue: one reduction + one atomic per block ----
    #pragma unroll
    for (int off = 16; off; off >>= 1)
        ssq_acc += __shfl_down_sync(0xffffffffu, ssq_acc, off);

    __shared__ float warpSums[NTHR / 32];
    if ((tid & 31) == 0) warpSums[tid >> 5] = ssq_acc;
    __syncthreads();
    if (tid == 0) {
        float v = warpSums[0] + warpSums[1] + warpSums[2] + warpSums[3];
        atomicAdd(&g_acc, (double)v);
    }
}

// ---------------------------------------------------------------------------
// Kernel 3: finalize
// ---------------------------------------------------------------------------
__global__ void finalize_kernel(float* __restrict__ out) {
    out[0] = sqrtf((float)g_acc);
}

extern "C" void kernel_launch(void* const* d_in, const int* in_sizes, int n_in,
                              void* d_out, int out_size) {
    const float* embeds = (const float*)d_in[0];   // class_embeds [100000, 50]
    const int*   nf1    = (const int*)d_in[1];     // nf1_data    [2000000, 2]

    int num_classes = in_sizes[0] / 50;
    if (num_classes > NUM_CLASSES) num_classes = NUM_CLASSES;
    int nPairs = in_sizes[1] / 2;

    // Precompute transformed table (warp per row) + zero accumulator
    int pre_blocks = (num_classes * 32 + 255) / 256;
    precompute_kernel<<<pre_blocks, 256>>>(embeds, num_classes);

    // Persistent pair kernel: 2 blocks/SM, double-buffered smem pipeline
    int smem_bytes = 2 * PPB * STRIDE4 * (int)sizeof(float4)
                   + 2 * 2 * PPB * (int)sizeof(int);
    cudaFuncSetAttribute(pair_kernel,
                         cudaFuncAttributeMaxDynamicSharedMemorySize, smem_bytes);

    int num_sms = 148;
    cudaDeviceGetAttribute(&num_sms, cudaDevAttrMultiProcessorCount, 0);
    int nTiles = (nPairs + PPB - 1) / PPB;
    int grid = 2 * num_sms;
    if (grid > nTiles) grid = nTiles;
    if (grid < 1) grid = 1;

    pair_kernel<<<grid, NTHR, smem_bytes>>>(nf1, nPairs, nTiles);

    finalize_kernel<<<1, 1>>>((float*)d_out);
}